// round 9
// baseline (speedup 1.0000x reference)
#include <cuda_runtime.h>
#include <math.h>

#define Bsz 256
#define Ssz 384
#define Dsz 192
#define Hsz 100
#define G4  400          // 4*H
#define Csz 250
#define Msz (Bsz*Ssz)    // 98304

// Scratch: __device__ globals (no runtime allocation allowed).
__device__ float g_pre[(size_t)Msz * G4];   // [B*S, 4H] = 157 MB
__device__ float g_h[Bsz * Hsz];            // final hidden states

// ---------------------------------------------------------------------------
// Phase 1: pre = X @ W + b     X:[M,192]  W:[192,400]  -> g_pre[M,400]
// 128x64 tile, 256 threads, 8x4 micro-tile, K-step 16. fp32.
// ---------------------------------------------------------------------------
#define TM 128
#define TN 64
#define TK 16
#define APAD 132   // pad to break STS bank conflicts; 132*4B is 16B-multiple

__global__ __launch_bounds__(256) void gemm_pre_kernel(
    const float* __restrict__ X, const float* __restrict__ W,
    const float* __restrict__ bias)
{
    __shared__ __align__(16) float As[TK][APAD];   // transposed: As[k][m]
    __shared__ __align__(16) float Bs[TK][TN];

    const int t  = threadIdx.x;
    const int bm = blockIdx.x * TM;
    const int bn = blockIdx.y * TN;
    const int ty = t >> 4;      // 0..15 -> 8 rows each
    const int tx = t & 15;      // 0..15 -> 4 cols each

    float acc[8][4] = {};

    for (int kk = 0; kk < Dsz; kk += TK) {
        // --- load A tile (128 rows x 16 k), store transposed ---
        #pragma unroll
        for (int it = 0; it < 2; it++) {
            int fid = t + it * 256;        // 0..511 float4 slots
            int row = fid >> 2;            // 0..127
            int kq  = fid & 3;             // 0..3
            float4 v = *(const float4*)(X + (size_t)(bm + row) * Dsz + kk + kq * 4);
            As[kq*4+0][row] = v.x;
            As[kq*4+1][row] = v.y;
            As[kq*4+2][row] = v.z;
            As[kq*4+3][row] = v.w;
        }
        // --- load B tile (16 k x 64 cols), guarded on N=400 ---
        {
            int krow = t >> 4;             // 0..15
            int cq   = t & 15;             // 0..15
            int col  = bn + cq * 4;
            float4 v = make_float4(0.f, 0.f, 0.f, 0.f);
            if (col < G4)
                v = *(const float4*)(W + (size_t)(kk + krow) * G4 + col);
            *(float4*)&Bs[krow][cq * 4] = v;
        }
        __syncthreads();

        #pragma unroll
        for (int k = 0; k < TK; k++) {
            float4 a0 = *(const float4*)&As[k][ty * 8];
            float4 a1 = *(const float4*)&As[k][ty * 8 + 4];
            float4 bv = *(const float4*)&Bs[k][tx * 4];
            float av[8] = {a0.x, a0.y, a0.z, a0.w, a1.x, a1.y, a1.z, a1.w};
            float bb[4] = {bv.x, bv.y, bv.z, bv.w};
            #pragma unroll
            for (int i = 0; i < 8; i++)
                #pragma unroll
                for (int j = 0; j < 4; j++)
                    acc[i][j] += av[i] * bb[j];
        }
        __syncthreads();
    }

    // epilogue: add bias, store (col guard is whole-float4 since 400 % 4 == 0)
    int col = bn + tx * 4;
    if (col < G4) {
        float4 bb = *(const float4*)(bias + col);
        #pragma unroll
        for (int i = 0; i < 8; i++) {
            int row = bm + ty * 8 + i;
            float4 o;
            o.x = acc[i][0] + bb.x;
            o.y = acc[i][1] + bb.y;
            o.z = acc[i][2] + bb.z;
            o.w = acc[i][3] + bb.w;
            *(float4*)(g_pre + (size_t)row * G4 + col) = o;
        }
    }
}

// ---------------------------------------------------------------------------
// Phase 2: LSTM recurrence.
// One block handles 2 batch rows. 128 blocks = 1 wave. 800 threads.
// Thread t: column k = t%400, j-half jh = t/400 (jh0: j 0..47, jh1: j 48..99).
// U slice lives in 52 registers/thread. h is read from smem via broadcast
// float4 loads. pre[t+1] is register-prefetched by the 200 gate threads.
// ---------------------------------------------------------------------------
__device__ __forceinline__ float sigf(float x) {
    return 1.0f / (1.0f + __expf(-x));
}

__global__ __launch_bounds__(800, 1) void lstm_kernel(const float* __restrict__ U)
{
    __shared__ __align__(16) float hsa[2][104];       // h for the 2 rows (padded)
    __shared__ float zbuf[2][2][G4];                  // [jh][row][k] partial sums

    const int t  = threadIdx.x;
    const int k  = t % 400;
    const int jh = t / 400;          // 0 or 1
    const int b0 = blockIdx.x * 2;

    // --- resident U slice: jh==0 -> j in [0,48), jh==1 -> j in [48,100) ---
    float Ur[52];
    #pragma unroll
    for (int jj = 0; jj < 52; jj++) {
        int j = jh * 48 + jj;
        bool valid = (jh == 1) || (jj < 48);
        Ur[jj] = valid ? U[j * 400 + k] : 0.0f;
    }

    // --- gate-thread state (t < 200): (row, m) ---
    const int grow = t / 100;
    const int gm   = t % 100;
    float c_state = 0.0f;
    float pr0 = 0.f, pr1 = 0.f, pr2 = 0.f, pr3 = 0.f;
    const float* Prow = g_pre;       // valid base; only used when t < 200
    if (t < 200) {
        hsa[grow][gm] = 0.0f;        // h0 = 0
        Prow = g_pre + (size_t)(b0 + grow) * Ssz * G4;
        pr0 = Prow[gm];
        pr1 = Prow[gm + 100];
        pr2 = Prow[gm + 200];
        pr3 = Prow[gm + 300];
    }
    __syncthreads();

    for (int step = 0; step < Ssz; step++) {
        // ---- GEMV: acc(row) = sum_j h[row][j] * U[j][k] over this jh half ----
        float acc0 = 0.f, acc1 = 0.f;
        const float* h0p = &hsa[0][jh * 48];   // 192B offset -> 16B aligned
        const float* h1p = &hsa[1][jh * 48];
        #pragma unroll
        for (int q = 0; q < 13; q++) {
            float4 h0 = *(const float4*)(h0p + 4 * q);   // broadcast across warp
            float4 h1 = *(const float4*)(h1p + 4 * q);
            acc0 += h0.x * Ur[4*q]   + h0.y * Ur[4*q+1]
                  + h0.z * Ur[4*q+2] + h0.w * Ur[4*q+3];
            acc1 += h1.x * Ur[4*q]   + h1.y * Ur[4*q+1]
                  + h1.z * Ur[4*q+2] + h1.w * Ur[4*q+3];
        }
        zbuf[jh][0][k] = acc0;
        zbuf[jh][1][k] = acc1;
        __syncthreads();   // h reads done + zbuf visible

        // ---- gates: 200 threads, one per (row, hidden unit) ----
        if (t < 200) {
            float zi = zbuf[0][grow][gm]       + zbuf[1][grow][gm]       + pr0;
            float zf = zbuf[0][grow][gm + 100] + zbuf[1][grow][gm + 100] + pr1;
            float zg = zbuf[0][grow][gm + 200] + zbuf[1][grow][gm + 200] + pr2;
            float zo = zbuf[0][grow][gm + 300] + zbuf[1][grow][gm + 300] + pr3;
            float ig = sigf(zi);
            float fg = sigf(zf);
            float gg = tanhf(zg);
            float og = sigf(zo);
            c_state = fg * c_state + ig * gg;
            float hn = og * tanhf(c_state);
            hsa[grow][gm] = hn;
            if (step + 1 < Ssz) {
                // prefetch next step's pre; latency hidden by next GEMV phase
                const float* P2 = Prow + (size_t)(step + 1) * G4;
                pr0 = P2[gm];
                pr1 = P2[gm + 100];
                pr2 = P2[gm + 200];
                pr3 = P2[gm + 300];
            } else {
                g_h[(b0 + grow) * Hsz + gm] = hn;
            }
        }
        __syncthreads();   // hn visible for next GEMV
    }
}

// ---------------------------------------------------------------------------
// Phase 3: out = hT @ Wd + bd     hT:[256,100]  Wd:[100,250]
// ---------------------------------------------------------------------------
__global__ __launch_bounds__(256) void classifier_kernel(
    const float* __restrict__ Wd, const float* __restrict__ bd,
    float* __restrict__ out)
{
    __shared__ float hrow[Hsz];
    const int b = blockIdx.x;
    const int t = threadIdx.x;
    if (t < Hsz) hrow[t] = g_h[b * Hsz + t];
    __syncthreads();
    if (t < Csz) {
        float s = bd[t];
        #pragma unroll 4
        for (int m = 0; m < Hsz; m++)
            s += hrow[m] * Wd[m * Csz + t];
        out[b * Csz + t] = s;
    }
}

// ---------------------------------------------------------------------------
extern "C" void kernel_launch(void* const* d_in, const int* in_sizes, int n_in,
                              void* d_out, int out_size)
{
    const float* x  = (const float*)d_in[0];   // [256,384,12,16]
    const float* W  = (const float*)d_in[1];   // [192,400]
    const float* U  = (const float*)d_in[2];   // [100,400]
    const float* b  = (const float*)d_in[3];   // [400]
    const float* Wd = (const float*)d_in[4];   // [100,250]
    const float* bd = (const float*)d_in[5];   // [250]
    float* out = (float*)d_out;                // [256,250]

    dim3 g1(Msz / TM, (G4 + TN - 1) / TN);     // 768 x 7
    gemm_pre_kernel<<<g1, 256>>>(x, W, b);
    lstm_kernel<<<Bsz / 2, 800>>>(U);
    classifier_kernel<<<Bsz, 256>>>(Wd, bd, out);
}

// round 10
// speedup vs baseline: 1.0017x; 1.0017x over previous
#include <cuda_runtime.h>
#include <math.h>

#define Bsz 256
#define Ssz 384
#define Dsz 192
#define Hsz 100
#define G4  400          // 4*H
#define Csz 250
#define Msz (Bsz*Ssz)    // 98304

// Scratch: __device__ globals (no runtime allocation allowed).
__device__ float g_pre[(size_t)Msz * G4];   // [B*S, 4H] = 157 MB
__device__ float g_h[Bsz * Hsz];            // final hidden states

// ---------------------------------------------------------------------------
// Phase 1: pre = X @ W + b     X:[M,192]  W:[192,400]  -> g_pre[M,400]
// 128x64 tile, 256 threads, 8x4 micro-tile, K-step 16. fp32.
// ---------------------------------------------------------------------------
#define TM 128
#define TN 64
#define TK 16
#define APAD 132   // pad to break STS bank conflicts; 132*4B is 16B-multiple

__global__ __launch_bounds__(256) void gemm_pre_kernel(
    const float* __restrict__ X, const float* __restrict__ W,
    const float* __restrict__ bias)
{
    __shared__ __align__(16) float As[TK][APAD];   // transposed: As[k][m]
    __shared__ __align__(16) float Bs[TK][TN];

    const int t  = threadIdx.x;
    const int bm = blockIdx.x * TM;
    const int bn = blockIdx.y * TN;
    const int ty = t >> 4;      // 0..15 -> 8 rows each
    const int tx = t & 15;      // 0..15 -> 4 cols each

    float acc[8][4] = {};

    for (int kk = 0; kk < Dsz; kk += TK) {
        // --- load A tile (128 rows x 16 k), store transposed ---
        #pragma unroll
        for (int it = 0; it < 2; it++) {
            int fid = t + it * 256;        // 0..511 float4 slots
            int row = fid >> 2;            // 0..127
            int kq  = fid & 3;             // 0..3
            float4 v = *(const float4*)(X + (size_t)(bm + row) * Dsz + kk + kq * 4);
            As[kq*4+0][row] = v.x;
            As[kq*4+1][row] = v.y;
            As[kq*4+2][row] = v.z;
            As[kq*4+3][row] = v.w;
        }
        // --- load B tile (16 k x 64 cols), guarded on N=400 ---
        {
            int krow = t >> 4;             // 0..15
            int cq   = t & 15;             // 0..15
            int col  = bn + cq * 4;
            float4 v = make_float4(0.f, 0.f, 0.f, 0.f);
            if (col < G4)
                v = *(const float4*)(W + (size_t)(kk + krow) * G4 + col);
            *(float4*)&Bs[krow][cq * 4] = v;
        }
        __syncthreads();

        #pragma unroll
        for (int k = 0; k < TK; k++) {
            float4 a0 = *(const float4*)&As[k][ty * 8];
            float4 a1 = *(const float4*)&As[k][ty * 8 + 4];
            float4 bv = *(const float4*)&Bs[k][tx * 4];
            float av[8] = {a0.x, a0.y, a0.z, a0.w, a1.x, a1.y, a1.z, a1.w};
            float bb[4] = {bv.x, bv.y, bv.z, bv.w};
            #pragma unroll
            for (int i = 0; i < 8; i++)
                #pragma unroll
                for (int j = 0; j < 4; j++)
                    acc[i][j] += av[i] * bb[j];
        }
        __syncthreads();
    }

    // epilogue: add bias, store (col guard is whole-float4 since 400 % 4 == 0)
    int col = bn + tx * 4;
    if (col < G4) {
        float4 bb = *(const float4*)(bias + col);
        #pragma unroll
        for (int i = 0; i < 8; i++) {
            int row = bm + ty * 8 + i;
            float4 o;
            o.x = acc[i][0] + bb.x;
            o.y = acc[i][1] + bb.y;
            o.z = acc[i][2] + bb.z;
            o.w = acc[i][3] + bb.w;
            *(float4*)(g_pre + (size_t)row * G4 + col) = o;
        }
    }
}

// ---------------------------------------------------------------------------
// Phase 2: LSTM recurrence.
// One block handles 2 batch rows. 128 blocks = 1 wave. 800 threads.
// Thread t: column k = t%400, j-half jh = t/400 (jh0: j 0..47, jh1: j 48..99).
// U slice lives in 52 registers/thread. h is read from smem via broadcast
// float4 loads. pre[t+1] is register-prefetched by the 200 gate threads.
// ---------------------------------------------------------------------------
__device__ __forceinline__ float sigf(float x) {
    return 1.0f / (1.0f + __expf(-x));
}

__global__ __launch_bounds__(800, 1) void lstm_kernel(const float* __restrict__ U)
{
    __shared__ __align__(16) float hsa[2][104];       // h for the 2 rows (padded)
    __shared__ float zbuf[2][2][G4];                  // [jh][row][k] partial sums

    const int t  = threadIdx.x;
    const int k  = t % 400;
    const int jh = t / 400;          // 0 or 1
    const int b0 = blockIdx.x * 2;

    // --- resident U slice: jh==0 -> j in [0,48), jh==1 -> j in [48,100) ---
    float Ur[52];
    #pragma unroll
    for (int jj = 0; jj < 52; jj++) {
        int j = jh * 48 + jj;
        bool valid = (jh == 1) || (jj < 48);
        Ur[jj] = valid ? U[j * 400 + k] : 0.0f;
    }

    // --- gate-thread state (t < 200): (row, m) ---
    const int grow = t / 100;
    const int gm   = t % 100;
    float c_state = 0.0f;
    float pr0 = 0.f, pr1 = 0.f, pr2 = 0.f, pr3 = 0.f;
    const float* Prow = g_pre;       // valid base; only used when t < 200
    if (t < 200) {
        hsa[grow][gm] = 0.0f;        // h0 = 0
        Prow = g_pre + (size_t)(b0 + grow) * Ssz * G4;
        pr0 = Prow[gm];
        pr1 = Prow[gm + 100];
        pr2 = Prow[gm + 200];
        pr3 = Prow[gm + 300];
    }
    __syncthreads();

    for (int step = 0; step < Ssz; step++) {
        // ---- GEMV: acc(row) = sum_j h[row][j] * U[j][k] over this jh half ----
        float acc0 = 0.f, acc1 = 0.f;
        const float* h0p = &hsa[0][jh * 48];   // 192B offset -> 16B aligned
        const float* h1p = &hsa[1][jh * 48];
        #pragma unroll
        for (int q = 0; q < 13; q++) {
            float4 h0 = *(const float4*)(h0p + 4 * q);   // broadcast across warp
            float4 h1 = *(const float4*)(h1p + 4 * q);
            acc0 += h0.x * Ur[4*q]   + h0.y * Ur[4*q+1]
                  + h0.z * Ur[4*q+2] + h0.w * Ur[4*q+3];
            acc1 += h1.x * Ur[4*q]   + h1.y * Ur[4*q+1]
                  + h1.z * Ur[4*q+2] + h1.w * Ur[4*q+3];
        }
        zbuf[jh][0][k] = acc0;
        zbuf[jh][1][k] = acc1;
        __syncthreads();   // h reads done + zbuf visible

        // ---- gates: 200 threads, one per (row, hidden unit) ----
        if (t < 200) {
            float zi = zbuf[0][grow][gm]       + zbuf[1][grow][gm]       + pr0;
            float zf = zbuf[0][grow][gm + 100] + zbuf[1][grow][gm + 100] + pr1;
            float zg = zbuf[0][grow][gm + 200] + zbuf[1][grow][gm + 200] + pr2;
            float zo = zbuf[0][grow][gm + 300] + zbuf[1][grow][gm + 300] + pr3;
            float ig = sigf(zi);
            float fg = sigf(zf);
            float gg = tanhf(zg);
            float og = sigf(zo);
            c_state = fg * c_state + ig * gg;
            float hn = og * tanhf(c_state);
            hsa[grow][gm] = hn;
            if (step + 1 < Ssz) {
                // prefetch next step's pre; latency hidden by next GEMV phase
                const float* P2 = Prow + (size_t)(step + 1) * G4;
                pr0 = P2[gm];
                pr1 = P2[gm + 100];
                pr2 = P2[gm + 200];
                pr3 = P2[gm + 300];
            } else {
                g_h[(b0 + grow) * Hsz + gm] = hn;
            }
        }
        __syncthreads();   // hn visible for next GEMV
    }
}

// ---------------------------------------------------------------------------
// Phase 3: out = hT @ Wd + bd     hT:[256,100]  Wd:[100,250]
// ---------------------------------------------------------------------------
__global__ __launch_bounds__(256) void classifier_kernel(
    const float* __restrict__ Wd, const float* __restrict__ bd,
    float* __restrict__ out)
{
    __shared__ float hrow[Hsz];
    const int b = blockIdx.x;
    const int t = threadIdx.x;
    if (t < Hsz) hrow[t] = g_h[b * Hsz + t];
    __syncthreads();
    if (t < Csz) {
        float s = bd[t];
        #pragma unroll 4
        for (int m = 0; m < Hsz; m++)
            s += hrow[m] * Wd[m * Csz + t];
        out[b * Csz + t] = s;
    }
}

// ---------------------------------------------------------------------------
extern "C" void kernel_launch(void* const* d_in, const int* in_sizes, int n_in,
                              void* d_out, int out_size)
{
    const float* x  = (const float*)d_in[0];   // [256,384,12,16]
    const float* W  = (const float*)d_in[1];   // [192,400]
    const float* U  = (const float*)d_in[2];   // [100,400]
    const float* b  = (const float*)d_in[3];   // [400]
    const float* Wd = (const float*)d_in[4];   // [100,250]
    const float* bd = (const float*)d_in[5];   // [250]
    float* out = (float*)d_out;                // [256,250]

    dim3 g1(Msz / TM, (G4 + TN - 1) / TN);     // 768 x 7
    gemm_pre_kernel<<<g1, 256>>>(x, W, b);
    lstm_kernel<<<Bsz / 2, 800>>>(U);
    classifier_kernel<<<Bsz, 256>>>(Wd, bd, out);
}

// round 11
// speedup vs baseline: 1.0053x; 1.0035x over previous
#include <cuda_runtime.h>
#include <math.h>

#define Bsz 256
#define Ssz 384
#define Dsz 192
#define Hsz 100
#define G4  400          // 4*H
#define Csz 250
#define Msz (Bsz*Ssz)    // 98304

// Scratch: __device__ globals (no runtime allocation allowed).
__device__ float g_pre[(size_t)Msz * G4];   // [B*S, 4H] = 157 MB
__device__ float g_h[Bsz * Hsz];            // final hidden states

// ---------------------------------------------------------------------------
// Phase 1: pre = X @ W + b     X:[M,192]  W:[192,400]  -> g_pre[M,400]
// 128x64 tile, 256 threads, 8x4 micro-tile, K-step 16. fp32.
// ---------------------------------------------------------------------------
#define TM 128
#define TN 64
#define TK 16
#define APAD 132   // pad to break STS bank conflicts; 132*4B is 16B-multiple

__global__ __launch_bounds__(256) void gemm_pre_kernel(
    const float* __restrict__ X, const float* __restrict__ W,
    const float* __restrict__ bias)
{
    __shared__ __align__(16) float As[TK][APAD];   // transposed: As[k][m]
    __shared__ __align__(16) float Bs[TK][TN];

    const int t  = threadIdx.x;
    const int bm = blockIdx.x * TM;
    const int bn = blockIdx.y * TN;
    const int ty = t >> 4;      // 0..15 -> 8 rows each
    const int tx = t & 15;      // 0..15 -> 4 cols each

    float acc[8][4] = {};

    for (int kk = 0; kk < Dsz; kk += TK) {
        // --- load A tile (128 rows x 16 k), store transposed ---
        #pragma unroll
        for (int it = 0; it < 2; it++) {
            int fid = t + it * 256;        // 0..511 float4 slots
            int row = fid >> 2;            // 0..127
            int kq  = fid & 3;             // 0..3
            float4 v = *(const float4*)(X + (size_t)(bm + row) * Dsz + kk + kq * 4);
            As[kq*4+0][row] = v.x;
            As[kq*4+1][row] = v.y;
            As[kq*4+2][row] = v.z;
            As[kq*4+3][row] = v.w;
        }
        // --- load B tile (16 k x 64 cols), guarded on N=400 ---
        {
            int krow = t >> 4;             // 0..15
            int cq   = t & 15;             // 0..15
            int col  = bn + cq * 4;
            float4 v = make_float4(0.f, 0.f, 0.f, 0.f);
            if (col < G4)
                v = *(const float4*)(W + (size_t)(kk + krow) * G4 + col);
            *(float4*)&Bs[krow][cq * 4] = v;
        }
        __syncthreads();

        #pragma unroll
        for (int k = 0; k < TK; k++) {
            float4 a0 = *(const float4*)&As[k][ty * 8];
            float4 a1 = *(const float4*)&As[k][ty * 8 + 4];
            float4 bv = *(const float4*)&Bs[k][tx * 4];
            float av[8] = {a0.x, a0.y, a0.z, a0.w, a1.x, a1.y, a1.z, a1.w};
            float bb[4] = {bv.x, bv.y, bv.z, bv.w};
            #pragma unroll
            for (int i = 0; i < 8; i++)
                #pragma unroll
                for (int j = 0; j < 4; j++)
                    acc[i][j] += av[i] * bb[j];
        }
        __syncthreads();
    }

    // epilogue: add bias, store (col guard is whole-float4 since 400 % 4 == 0)
    int col = bn + tx * 4;
    if (col < G4) {
        float4 bb = *(const float4*)(bias + col);
        #pragma unroll
        for (int i = 0; i < 8; i++) {
            int row = bm + ty * 8 + i;
            float4 o;
            o.x = acc[i][0] + bb.x;
            o.y = acc[i][1] + bb.y;
            o.z = acc[i][2] + bb.z;
            o.w = acc[i][3] + bb.w;
            *(float4*)(g_pre + (size_t)row * G4 + col) = o;
        }
    }
}

// ---------------------------------------------------------------------------
// Phase 2: LSTM recurrence.
// One block handles 2 batch rows. 128 blocks = 1 wave. 800 threads.
// Thread t: column k = t%400, j-half jh = t/400 (jh0: j 0..47, jh1: j 48..99).
// U slice lives in 52 registers/thread. h is read from smem via broadcast
// float4 loads. pre[t+1] is register-prefetched by the 200 gate threads.
// ---------------------------------------------------------------------------
__device__ __forceinline__ float sigf(float x) {
    return 1.0f / (1.0f + __expf(-x));
}

__global__ __launch_bounds__(800, 1) void lstm_kernel(const float* __restrict__ U)
{
    __shared__ __align__(16) float hsa[2][104];       // h for the 2 rows (padded)
    __shared__ float zbuf[2][2][G4];                  // [jh][row][k] partial sums

    const int t  = threadIdx.x;
    const int k  = t % 400;
    const int jh = t / 400;          // 0 or 1
    const int b0 = blockIdx.x * 2;

    // --- resident U slice: jh==0 -> j in [0,48), jh==1 -> j in [48,100) ---
    float Ur[52];
    #pragma unroll
    for (int jj = 0; jj < 52; jj++) {
        int j = jh * 48 + jj;
        bool valid = (jh == 1) || (jj < 48);
        Ur[jj] = valid ? U[j * 400 + k] : 0.0f;
    }

    // --- gate-thread state (t < 200): (row, m) ---
    const int grow = t / 100;
    const int gm   = t % 100;
    float c_state = 0.0f;
    float pr0 = 0.f, pr1 = 0.f, pr2 = 0.f, pr3 = 0.f;
    const float* Prow = g_pre;       // valid base; only used when t < 200
    if (t < 200) {
        hsa[grow][gm] = 0.0f;        // h0 = 0
        Prow = g_pre + (size_t)(b0 + grow) * Ssz * G4;
        pr0 = Prow[gm];
        pr1 = Prow[gm + 100];
        pr2 = Prow[gm + 200];
        pr3 = Prow[gm + 300];
    }
    __syncthreads();

    for (int step = 0; step < Ssz; step++) {
        // ---- GEMV: acc(row) = sum_j h[row][j] * U[j][k] over this jh half ----
        float acc0 = 0.f, acc1 = 0.f;
        const float* h0p = &hsa[0][jh * 48];   // 192B offset -> 16B aligned
        const float* h1p = &hsa[1][jh * 48];
        #pragma unroll
        for (int q = 0; q < 13; q++) {
            float4 h0 = *(const float4*)(h0p + 4 * q);   // broadcast across warp
            float4 h1 = *(const float4*)(h1p + 4 * q);
            acc0 += h0.x * Ur[4*q]   + h0.y * Ur[4*q+1]
                  + h0.z * Ur[4*q+2] + h0.w * Ur[4*q+3];
            acc1 += h1.x * Ur[4*q]   + h1.y * Ur[4*q+1]
                  + h1.z * Ur[4*q+2] + h1.w * Ur[4*q+3];
        }
        zbuf[jh][0][k] = acc0;
        zbuf[jh][1][k] = acc1;
        __syncthreads();   // h reads done + zbuf visible

        // ---- gates: 200 threads, one per (row, hidden unit) ----
        if (t < 200) {
            float zi = zbuf[0][grow][gm]       + zbuf[1][grow][gm]       + pr0;
            float zf = zbuf[0][grow][gm + 100] + zbuf[1][grow][gm + 100] + pr1;
            float zg = zbuf[0][grow][gm + 200] + zbuf[1][grow][gm + 200] + pr2;
            float zo = zbuf[0][grow][gm + 300] + zbuf[1][grow][gm + 300] + pr3;
            float ig = sigf(zi);
            float fg = sigf(zf);
            float gg = tanhf(zg);
            float og = sigf(zo);
            c_state = fg * c_state + ig * gg;
            float hn = og * tanhf(c_state);
            hsa[grow][gm] = hn;
            if (step + 1 < Ssz) {
                // prefetch next step's pre; latency hidden by next GEMV phase
                const float* P2 = Prow + (size_t)(step + 1) * G4;
                pr0 = P2[gm];
                pr1 = P2[gm + 100];
                pr2 = P2[gm + 200];
                pr3 = P2[gm + 300];
            } else {
                g_h[(b0 + grow) * Hsz + gm] = hn;
            }
        }
        __syncthreads();   // hn visible for next GEMV
    }
}

// ---------------------------------------------------------------------------
// Phase 3: out = hT @ Wd + bd     hT:[256,100]  Wd:[100,250]
// ---------------------------------------------------------------------------
__global__ __launch_bounds__(256) void classifier_kernel(
    const float* __restrict__ Wd, const float* __restrict__ bd,
    float* __restrict__ out)
{
    __shared__ float hrow[Hsz];
    const int b = blockIdx.x;
    const int t = threadIdx.x;
    if (t < Hsz) hrow[t] = g_h[b * Hsz + t];
    __syncthreads();
    if (t < Csz) {
        float s = bd[t];
        #pragma unroll 4
        for (int m = 0; m < Hsz; m++)
            s += hrow[m] * Wd[m * Csz + t];
        out[b * Csz + t] = s;
    }
}

// ---------------------------------------------------------------------------
extern "C" void kernel_launch(void* const* d_in, const int* in_sizes, int n_in,
                              void* d_out, int out_size)
{
    const float* x  = (const float*)d_in[0];   // [256,384,12,16]
    const float* W  = (const float*)d_in[1];   // [192,400]
    const float* U  = (const float*)d_in[2];   // [100,400]
    const float* b  = (const float*)d_in[3];   // [400]
    const float* Wd = (const float*)d_in[4];   // [100,250]
    const float* bd = (const float*)d_in[5];   // [250]
    float* out = (float*)d_out;                // [256,250]

    dim3 g1(Msz / TM, (G4 + TN - 1) / TN);     // 768 x 7
    gemm_pre_kernel<<<g1, 256>>>(x, W, b);
    lstm_kernel<<<Bsz / 2, 800>>>(U);
    classifier_kernel<<<Bsz, 256>>>(Wd, bd, out);
}

// round 12
// speedup vs baseline: 1.0134x; 1.0081x over previous
#include <cuda_runtime.h>
#include <math.h>

#define Bsz 256
#define Ssz 384
#define Dsz 192
#define Hsz 100
#define G4  400          // 4*H
#define Csz 250
#define Msz (Bsz*Ssz)    // 98304

// Scratch: __device__ globals (no runtime allocation allowed).
__device__ float g_pre[(size_t)Msz * G4];   // [B*S, 4H] = 157 MB
__device__ float g_h[Bsz * Hsz];            // final hidden states

// ---------------------------------------------------------------------------
// Phase 1: pre = X @ W + b     X:[M,192]  W:[192,400]  -> g_pre[M,400]
// 128x64 tile, 256 threads, 8x4 micro-tile, K-step 16. fp32.
// ---------------------------------------------------------------------------
#define TM 128
#define TN 64
#define TK 16
#define APAD 132   // pad to break STS bank conflicts; 132*4B is 16B-multiple

__global__ __launch_bounds__(256) void gemm_pre_kernel(
    const float* __restrict__ X, const float* __restrict__ W,
    const float* __restrict__ bias)
{
    __shared__ __align__(16) float As[TK][APAD];   // transposed: As[k][m]
    __shared__ __align__(16) float Bs[TK][TN];

    const int t  = threadIdx.x;
    const int bm = blockIdx.x * TM;
    const int bn = blockIdx.y * TN;
    const int ty = t >> 4;      // 0..15 -> 8 rows each
    const int tx = t & 15;      // 0..15 -> 4 cols each

    float acc[8][4] = {};

    for (int kk = 0; kk < Dsz; kk += TK) {
        // --- load A tile (128 rows x 16 k), store transposed ---
        #pragma unroll
        for (int it = 0; it < 2; it++) {
            int fid = t + it * 256;        // 0..511 float4 slots
            int row = fid >> 2;            // 0..127
            int kq  = fid & 3;             // 0..3
            float4 v = *(const float4*)(X + (size_t)(bm + row) * Dsz + kk + kq * 4);
            As[kq*4+0][row] = v.x;
            As[kq*4+1][row] = v.y;
            As[kq*4+2][row] = v.z;
            As[kq*4+3][row] = v.w;
        }
        // --- load B tile (16 k x 64 cols), guarded on N=400 ---
        {
            int krow = t >> 4;             // 0..15
            int cq   = t & 15;             // 0..15
            int col  = bn + cq * 4;
            float4 v = make_float4(0.f, 0.f, 0.f, 0.f);
            if (col < G4)
                v = *(const float4*)(W + (size_t)(kk + krow) * G4 + col);
            *(float4*)&Bs[krow][cq * 4] = v;
        }
        __syncthreads();

        #pragma unroll
        for (int k = 0; k < TK; k++) {
            float4 a0 = *(const float4*)&As[k][ty * 8];
            float4 a1 = *(const float4*)&As[k][ty * 8 + 4];
            float4 bv = *(const float4*)&Bs[k][tx * 4];
            float av[8] = {a0.x, a0.y, a0.z, a0.w, a1.x, a1.y, a1.z, a1.w};
            float bb[4] = {bv.x, bv.y, bv.z, bv.w};
            #pragma unroll
            for (int i = 0; i < 8; i++)
                #pragma unroll
                for (int j = 0; j < 4; j++)
                    acc[i][j] += av[i] * bb[j];
        }
        __syncthreads();
    }

    // epilogue: add bias, store (col guard is whole-float4 since 400 % 4 == 0)
    int col = bn + tx * 4;
    if (col < G4) {
        float4 bb = *(const float4*)(bias + col);
        #pragma unroll
        for (int i = 0; i < 8; i++) {
            int row = bm + ty * 8 + i;
            float4 o;
            o.x = acc[i][0] + bb.x;
            o.y = acc[i][1] + bb.y;
            o.z = acc[i][2] + bb.z;
            o.w = acc[i][3] + bb.w;
            *(float4*)(g_pre + (size_t)row * G4 + col) = o;
        }
    }
}

// ---------------------------------------------------------------------------
// Phase 2: LSTM recurrence.
// One block handles 2 batch rows. 128 blocks = 1 wave. 800 threads.
// Thread t: column k = t%400, j-half jh = t/400 (jh0: j 0..47, jh1: j 48..99).
// U slice lives in 52 registers/thread. h is read from smem via broadcast
// float4 loads. pre[t+1] is register-prefetched by the 200 gate threads.
// ---------------------------------------------------------------------------
__device__ __forceinline__ float sigf(float x) {
    return 1.0f / (1.0f + __expf(-x));
}

__global__ __launch_bounds__(800, 1) void lstm_kernel(const float* __restrict__ U)
{
    __shared__ __align__(16) float hsa[2][104];       // h for the 2 rows (padded)
    __shared__ float zbuf[2][2][G4];                  // [jh][row][k] partial sums

    const int t  = threadIdx.x;
    const int k  = t % 400;
    const int jh = t / 400;          // 0 or 1
    const int b0 = blockIdx.x * 2;

    // --- resident U slice: jh==0 -> j in [0,48), jh==1 -> j in [48,100) ---
    float Ur[52];
    #pragma unroll
    for (int jj = 0; jj < 52; jj++) {
        int j = jh * 48 + jj;
        bool valid = (jh == 1) || (jj < 48);
        Ur[jj] = valid ? U[j * 400 + k] : 0.0f;
    }

    // --- gate-thread state (t < 200): (row, m) ---
    const int grow = t / 100;
    const int gm   = t % 100;
    float c_state = 0.0f;
    float pr0 = 0.f, pr1 = 0.f, pr2 = 0.f, pr3 = 0.f;
    const float* Prow = g_pre;       // valid base; only used when t < 200
    if (t < 200) {
        hsa[grow][gm] = 0.0f;        // h0 = 0
        Prow = g_pre + (size_t)(b0 + grow) * Ssz * G4;
        pr0 = Prow[gm];
        pr1 = Prow[gm + 100];
        pr2 = Prow[gm + 200];
        pr3 = Prow[gm + 300];
    }
    __syncthreads();

    for (int step = 0; step < Ssz; step++) {
        // ---- GEMV: acc(row) = sum_j h[row][j] * U[j][k] over this jh half ----
        float acc0 = 0.f, acc1 = 0.f;
        const float* h0p = &hsa[0][jh * 48];   // 192B offset -> 16B aligned
        const float* h1p = &hsa[1][jh * 48];
        #pragma unroll
        for (int q = 0; q < 13; q++) {
            float4 h0 = *(const float4*)(h0p + 4 * q);   // broadcast across warp
            float4 h1 = *(const float4*)(h1p + 4 * q);
            acc0 += h0.x * Ur[4*q]   + h0.y * Ur[4*q+1]
                  + h0.z * Ur[4*q+2] + h0.w * Ur[4*q+3];
            acc1 += h1.x * Ur[4*q]   + h1.y * Ur[4*q+1]
                  + h1.z * Ur[4*q+2] + h1.w * Ur[4*q+3];
        }
        zbuf[jh][0][k] = acc0;
        zbuf[jh][1][k] = acc1;
        __syncthreads();   // h reads done + zbuf visible

        // ---- gates: 200 threads, one per (row, hidden unit) ----
        if (t < 200) {
            float zi = zbuf[0][grow][gm]       + zbuf[1][grow][gm]       + pr0;
            float zf = zbuf[0][grow][gm + 100] + zbuf[1][grow][gm + 100] + pr1;
            float zg = zbuf[0][grow][gm + 200] + zbuf[1][grow][gm + 200] + pr2;
            float zo = zbuf[0][grow][gm + 300] + zbuf[1][grow][gm + 300] + pr3;
            float ig = sigf(zi);
            float fg = sigf(zf);
            float gg = tanhf(zg);
            float og = sigf(zo);
            c_state = fg * c_state + ig * gg;
            float hn = og * tanhf(c_state);
            hsa[grow][gm] = hn;
            if (step + 1 < Ssz) {
                // prefetch next step's pre; latency hidden by next GEMV phase
                const float* P2 = Prow + (size_t)(step + 1) * G4;
                pr0 = P2[gm];
                pr1 = P2[gm + 100];
                pr2 = P2[gm + 200];
                pr3 = P2[gm + 300];
            } else {
                g_h[(b0 + grow) * Hsz + gm] = hn;
            }
        }
        __syncthreads();   // hn visible for next GEMV
    }
}

// ---------------------------------------------------------------------------
// Phase 3: out = hT @ Wd + bd     hT:[256,100]  Wd:[100,250]
// ---------------------------------------------------------------------------
__global__ __launch_bounds__(256) void classifier_kernel(
    const float* __restrict__ Wd, const float* __restrict__ bd,
    float* __restrict__ out)
{
    __shared__ float hrow[Hsz];
    const int b = blockIdx.x;
    const int t = threadIdx.x;
    if (t < Hsz) hrow[t] = g_h[b * Hsz + t];
    __syncthreads();
    if (t < Csz) {
        float s = bd[t];
        #pragma unroll 4
        for (int m = 0; m < Hsz; m++)
            s += hrow[m] * Wd[m * Csz + t];
        out[b * Csz + t] = s;
    }
}

// ---------------------------------------------------------------------------
extern "C" void kernel_launch(void* const* d_in, const int* in_sizes, int n_in,
                              void* d_out, int out_size)
{
    const float* x  = (const float*)d_in[0];   // [256,384,12,16]
    const float* W  = (const float*)d_in[1];   // [192,400]
    const float* U  = (const float*)d_in[2];   // [100,400]
    const float* b  = (const float*)d_in[3];   // [400]
    const float* Wd = (const float*)d_in[4];   // [100,250]
    const float* bd = (const float*)d_in[5];   // [250]
    float* out = (float*)d_out;                // [256,250]

    dim3 g1(Msz / TM, (G4 + TN - 1) / TN);     // 768 x 7
    gemm_pre_kernel<<<g1, 256>>>(x, W, b);
    lstm_kernel<<<Bsz / 2, 800>>>(U);
    classifier_kernel<<<Bsz, 256>>>(Wd, bd, out);
}